// round 1
// baseline (speedup 1.0000x reference)
#include <cuda_runtime.h>

// Problem constants (fixed by the dataset):
//   tokens: int32[4194304], ls: float32[128,2,2], final: float32[2,1] (unused by ref)
//   output: float32[2] = row 0 of ordered product of ls[tokens[t]], last token applied twice.

#define TPB 256
#define TOK_PER_THREAD 16
#define TOK_PER_BLOCK (TPB * TOK_PER_THREAD)   // 4096
#define MAX_BLOCKS 4096

// Per-block partial products (row-major 2x2 packed as float4 = m00,m01,m10,m11)
__device__ float4 g_part[MAX_BLOCKS];

// C = A @ B for row-major 2x2 packed (x=m00, y=m01, z=m10, w=m11)
__device__ __forceinline__ float4 mm2(float4 A, float4 B) {
    float4 C;
    C.x = fmaf(A.x, B.x, A.y * B.z);
    C.y = fmaf(A.x, B.y, A.y * B.w);
    C.z = fmaf(A.z, B.x, A.w * B.z);
    C.w = fmaf(A.z, B.y, A.w * B.w);
    return C;
}

// Order-preserving pairwise-adjacent warp reduction: after round `off`,
// lanes with lane % (2*off) == 0 hold the product of lanes [lane, lane+2*off).
__device__ __forceinline__ float4 warp_reduce_ordered(float4 M, unsigned lane) {
    #pragma unroll
    for (int off = 1; off < 32; off <<= 1) {
        float4 B;
        B.x = __shfl_down_sync(0xffffffffu, M.x, off);
        B.y = __shfl_down_sync(0xffffffffu, M.y, off);
        B.z = __shfl_down_sync(0xffffffffu, M.z, off);
        B.w = __shfl_down_sync(0xffffffffu, M.w, off);
        if ((lane & (2 * off - 1)) == 0) M = mm2(M, B);
    }
    return M;
}

__global__ void __launch_bounds__(TPB)
chain_partial_kernel(const int* __restrict__ tokens,
                     const float* __restrict__ ls) {
    __shared__ float4 s_ls[128];     // 2 KB transition table
    __shared__ float4 s_warp[TPB / 32];

    const unsigned tid  = threadIdx.x;
    const unsigned lane = tid & 31u;
    const unsigned wid  = tid >> 5;

    if (tid < 128) s_ls[tid] = reinterpret_cast<const float4*>(ls)[tid];
    __syncthreads();

    // This thread's 16 contiguous tokens, read as 4x int4.
    const int4* __restrict__ tok4 = reinterpret_cast<const int4*>(tokens);
    const unsigned i4_base = (blockIdx.x * TPB + tid) * (TOK_PER_THREAD / 4);

    int4 t0 = tok4[i4_base + 0];
    int4 t1 = tok4[i4_base + 1];
    int4 t2 = tok4[i4_base + 2];
    int4 t3 = tok4[i4_base + 3];

    float4 M = s_ls[t0.x];
    M = mm2(M, s_ls[t0.y]);
    M = mm2(M, s_ls[t0.z]);
    M = mm2(M, s_ls[t0.w]);
    M = mm2(M, s_ls[t1.x]);
    M = mm2(M, s_ls[t1.y]);
    M = mm2(M, s_ls[t1.z]);
    M = mm2(M, s_ls[t1.w]);
    M = mm2(M, s_ls[t2.x]);
    M = mm2(M, s_ls[t2.y]);
    M = mm2(M, s_ls[t2.z]);
    M = mm2(M, s_ls[t2.w]);
    M = mm2(M, s_ls[t3.x]);
    M = mm2(M, s_ls[t3.y]);
    M = mm2(M, s_ls[t3.z]);
    M = mm2(M, s_ls[t3.w]);

    M = warp_reduce_ordered(M, lane);

    if (lane == 0) s_warp[wid] = M;
    __syncthreads();

    if (tid == 0) {
        float4 R = s_warp[0];
        #pragma unroll
        for (int w = 1; w < TPB / 32; w++) R = mm2(R, s_warp[w]);
        g_part[blockIdx.x] = R;
    }
}

__global__ void __launch_bounds__(TPB)
chain_final_kernel(const int* __restrict__ tokens,
                   const float* __restrict__ ls,
                   float* __restrict__ out,
                   int n_part, int n_tokens) {
    __shared__ float4 s_warp[TPB / 32];

    const unsigned tid  = threadIdx.x;
    const unsigned lane = tid & 31u;
    const unsigned wid  = tid >> 5;

    const int per_thread = n_part / TPB;   // 1024/256 = 4
    const int base = tid * per_thread;

    float4 M = g_part[base];
    for (int i = 1; i < per_thread; i++) M = mm2(M, g_part[base + i]);

    M = warp_reduce_ordered(M, lane);

    if (lane == 0) s_warp[wid] = M;
    __syncthreads();

    if (tid == 0) {
        float4 R = s_warp[0];
        #pragma unroll
        for (int w = 1; w < TPB / 32; w++) R = mm2(R, s_warp[w]);

        // Faithful to reference: apply the last token's matrix one extra time.
        int last = tokens[n_tokens - 1];
        float4 B = reinterpret_cast<const float4*>(ls)[last];
        R = mm2(R, B);

        // v = [1,0] @ R  ->  row 0 of R
        out[0] = R.x;
        out[1] = R.y;
    }
}

extern "C" void kernel_launch(void* const* d_in, const int* in_sizes, int n_in,
                              void* d_out, int out_size) {
    const int*   tokens = (const int*)d_in[0];
    const float* ls     = (const float*)d_in[1];
    // d_in[2] = final (unused by the reference computation)
    float* out = (float*)d_out;

    const int n = in_sizes[0];                 // 4194304
    const int nblocks = n / TOK_PER_BLOCK;     // 1024

    chain_partial_kernel<<<nblocks, TPB>>>(tokens, ls);
    chain_final_kernel<<<1, TPB>>>(tokens, ls, out, nblocks, n);
}

// round 2
// speedup vs baseline: 1.0503x; 1.0503x over previous
#include <cuda_runtime.h>

// Problem constants (fixed by the dataset):
//   tokens: int32[4194304], ls: float32[128,2,2], final: float32[2,1] (unused)
//   output: float32[2] = row 0 of ordered product of ls[tokens[t]], last token applied twice.

#define TPB 256
#define TOK_PER_THREAD 16
#define TOK_PER_BLOCK (TPB * TOK_PER_THREAD)   // 4096
#define MAX_BLOCKS 4096

// Per-block partial products (row-major 2x2 packed as float4 = m00,m01,m10,m11)
__device__ float4 g_part[MAX_BLOCKS];
__device__ unsigned g_count = 0;   // last-block detector; reset by last block each call

// C = A @ B for row-major 2x2 packed (x=m00, y=m01, z=m10, w=m11)
__device__ __forceinline__ float4 mm2(float4 A, float4 B) {
    float4 C;
    C.x = fmaf(A.x, B.x, A.y * B.z);
    C.y = fmaf(A.x, B.y, A.y * B.w);
    C.z = fmaf(A.z, B.x, A.w * B.z);
    C.w = fmaf(A.z, B.y, A.w * B.w);
    return C;
}

// Order-preserving pairwise-adjacent warp reduction: lane 0 ends with the
// ordered product of all 32 lanes' matrices.
__device__ __forceinline__ float4 warp_reduce_ordered(float4 M, unsigned lane) {
    #pragma unroll
    for (int off = 1; off < 32; off <<= 1) {
        float4 B;
        B.x = __shfl_down_sync(0xffffffffu, M.x, off);
        B.y = __shfl_down_sync(0xffffffffu, M.y, off);
        B.z = __shfl_down_sync(0xffffffffu, M.z, off);
        B.w = __shfl_down_sync(0xffffffffu, M.w, off);
        if ((lane & (2 * off - 1)) == 0) M = mm2(M, B);
    }
    return M;
}

__global__ void __launch_bounds__(TPB)
chain_fused_kernel(const int* __restrict__ tokens,
                   const float* __restrict__ ls,
                   float* __restrict__ out,
                   int n_tokens) {
    __shared__ float4 s_ls[128];        // 2 KB transition table
    __shared__ float4 s_warp[TPB / 32];
    __shared__ bool   s_is_last;

    const unsigned tid  = threadIdx.x;
    const unsigned lane = tid & 31u;
    const unsigned wid  = tid >> 5;
    const unsigned nblk = gridDim.x;

    if (tid < 128) s_ls[tid] = reinterpret_cast<const float4*>(ls)[tid];
    __syncthreads();

    // ── Phase 1: per-thread ordered product of 16 contiguous tokens,
    //    as TWO independent 8-chains for 2x ILP, combined at the end.
    const int4* __restrict__ tok4 = reinterpret_cast<const int4*>(tokens);
    const unsigned i4_base = (blockIdx.x * TPB + tid) * (TOK_PER_THREAD / 4);

    int4 t0 = tok4[i4_base + 0];
    int4 t1 = tok4[i4_base + 1];
    int4 t2 = tok4[i4_base + 2];
    int4 t3 = tok4[i4_base + 3];

    float4 A = s_ls[t0.x];
    float4 B = s_ls[t2.x];
    A = mm2(A, s_ls[t0.y]);  B = mm2(B, s_ls[t2.y]);
    A = mm2(A, s_ls[t0.z]);  B = mm2(B, s_ls[t2.z]);
    A = mm2(A, s_ls[t0.w]);  B = mm2(B, s_ls[t2.w]);
    A = mm2(A, s_ls[t1.x]);  B = mm2(B, s_ls[t3.x]);
    A = mm2(A, s_ls[t1.y]);  B = mm2(B, s_ls[t3.y]);
    A = mm2(A, s_ls[t1.z]);  B = mm2(B, s_ls[t3.z]);
    A = mm2(A, s_ls[t1.w]);  B = mm2(B, s_ls[t3.w]);
    float4 M = mm2(A, B);

    // ── Phase 2: ordered block reduction -> one partial per block
    M = warp_reduce_ordered(M, lane);
    if (lane == 0) s_warp[wid] = M;
    __syncthreads();

    if (tid == 0) {
        float4 R = s_warp[0];
        #pragma unroll
        for (int w = 1; w < TPB / 32; w++) R = mm2(R, s_warp[w]);
        g_part[blockIdx.x] = R;
        __threadfence();                       // publish partial before counting
        unsigned old = atomicAdd(&g_count, 1u);
        s_is_last = (old == nblk - 1);
    }
    __syncthreads();

    // ── Phase 3: last block combines all partials in order
    if (s_is_last) {
        __threadfence();                       // order reads after all publishes
        const int per_thread = (int)(nblk / TPB);      // 1024/256 = 4
        const int base = tid * per_thread;

        float4 P = g_part[base];
        for (int i = 1; i < per_thread; i++) P = mm2(P, g_part[base + i]);

        P = warp_reduce_ordered(P, lane);
        if (lane == 0) s_warp[wid] = P;
        __syncthreads();

        if (tid == 0) {
            float4 R = s_warp[0];
            #pragma unroll
            for (int w = 1; w < TPB / 32; w++) R = mm2(R, s_warp[w]);

            // Faithful to reference: apply the last token's matrix one extra time.
            int last = tokens[n_tokens - 1];
            R = mm2(R, s_ls[last]);

            // v = [1,0] @ R  ->  row 0 of R
            out[0] = R.x;
            out[1] = R.y;

            __threadfence();
            atomicExch(&g_count, 0u);          // reset for next (deterministic) call
        }
    }
}

extern "C" void kernel_launch(void* const* d_in, const int* in_sizes, int n_in,
                              void* d_out, int out_size) {
    const int*   tokens = (const int*)d_in[0];
    const float* ls     = (const float*)d_in[1];
    float* out = (float*)d_out;

    const int n = in_sizes[0];                 // 4194304
    const int nblocks = n / TOK_PER_BLOCK;     // 1024

    chain_fused_kernel<<<nblocks, TPB>>>(tokens, ls, out, n);
}